// round 4
// baseline (speedup 1.0000x reference)
#include <cuda_runtime.h>
#include <cstdint>

#define DM    1024
#define DFF   2048
#define NROWS 32768
#define MAXT  264
#define PADROWS (MAXT*128)

// ---------------- scratch ----------------
__device__ float g_Xr [(size_t)PADROWS*DM];    // gathered x rows, tf32-rounded
__device__ float g_ACT[(size_t)PADROWS*DFF];   // GLU activations, tf32-rounded
__device__ float g_W1p[(size_t)8*4096*DM];     // W1 packed for mma B-frags (h||gate paired)
__device__ float g_W2p[(size_t)8*DM*DFF];      // W2 packed
__device__ int   g_perm[PADROWS];
__device__ int   g_cnt[8];
__device__ int   g_tb[9];
__device__ unsigned g_det;                      // 0 -> indices are int64, else int32

// ---------------- helpers ----------------
__device__ __forceinline__ float rtf(float a){ asm("cvt.rna.tf32.f32 %0, %0;":"+f"(a)); return a; }
__device__ __forceinline__ uint32_t fu(float f){ return __float_as_uint(f); }
__device__ __forceinline__ uint32_t su32(const void* p){
  uint32_t a; asm("{ .reg .u64 t; cvta.to.shared.u64 t, %1; cvt.u32.u64 %0, t; }":"=r"(a):"l"(p)); return a;
}
__device__ __forceinline__ void cp16(uint32_t d, const void* s){
  asm volatile("cp.async.cg.shared.global [%0], [%1], 16;" :: "r"(d), "l"(s) : "memory");
}
#define CPCOMMIT() asm volatile("cp.async.commit_group;":::"memory")
#define CPWAIT(n)  asm volatile("cp.async.wait_group %0;"::"n"(n):"memory")

__device__ __forceinline__ void mma8(float* c, const uint32_t* a, uint32_t b0, uint32_t b1){
  asm volatile("mma.sync.aligned.m16n8k8.row.col.f32.tf32.tf32.f32 "
    "{%0,%1,%2,%3},{%4,%5,%6,%7},{%8,%9},{%0,%1,%2,%3};"
    : "+f"(c[0]),"+f"(c[1]),"+f"(c[2]),"+f"(c[3])
    : "r"(a[0]),"r"(a[1]),"r"(a[2]),"r"(a[3]),"r"(b0),"r"(b1));
}

// ---------------- setup ----------------
__global__ void k_setupA(const int* __restrict__ counts){
  if (threadIdx.x==0){
    int tb=0;
    for (int e=0;e<8;e++){ g_tb[e]=tb; g_cnt[e]=0; tb += (counts[e]+127)>>7; }
    g_tb[8]=tb;
    g_det = 0u;
  }
}
__global__ void k_setupB(){
  for (int i = blockIdx.x*blockDim.x + threadIdx.x; i<PADROWS; i += gridDim.x*blockDim.x)
    g_perm[i] = -1;
}

// ---------------- indices dtype detection ----------------
// Scan odd 32-bit words among the first 16384 pairs (safe under both dtypes:
// 32768 int32 words exist either way). int64 indices (values 0..7) -> all high
// halves zero -> g_det stays 0. int32 indices -> words are expert ids, some
// nonzero with overwhelming probability -> g_det != 0.
__global__ void k_detect(const unsigned* __restrict__ w){
  unsigned v = 0;
  for (int i = blockIdx.x*blockDim.x + threadIdx.x; i < 16384; i += gridDim.x*blockDim.x)
    v |= w[2*i+1];
  #pragma unroll
  for (int o=16;o>0;o>>=1) v |= __shfl_xor_sync(0xFFFFFFFFu, v, o);
  if ((threadIdx.x&31)==0 && v) atomicOr(&g_det, v);
}

// ---------------- gather: perm + rounded row copy ----------------
__global__ void k_gather(const float* __restrict__ x, const void* __restrict__ ind){
  __shared__ int ss;
  int p = blockIdx.x;
  if (threadIdx.x==0){
    int e;
    if (g_det==0u) e = (int)((const long long*)ind)[p];   // int64
    else           e = ((const int*)ind)[p];              // int32
    e &= 7;
    int s = (g_tb[e]<<7) + atomicAdd(&g_cnt[e],1);
    if (s >= PADROWS) s = PADROWS-1;                      // safety only
    g_perm[s] = p; ss = s;
  }
  __syncthreads();
  int s = ss;
  float4 v = *(const float4*)(x + (size_t)(p>>1)*DM + threadIdx.x*4);
  v.x=rtf(v.x); v.y=rtf(v.y); v.z=rtf(v.z); v.w=rtf(v.w);
  *(float4*)(g_Xr + (size_t)s*DM + threadIdx.x*4) = v;
}

// ---------------- weight pack kernels ----------------
// Packed B layout per 16-K chunk, per 64-col colblk (4KB):
//   float4 index q = [cb(2b)][s(1b)][qq(2b)][lane(5b)]
//   v = { B(n0,k0), B(n0,k0+4), B(n0+8,k0), B(n0+8,k0+4) },
//   n0 = cb*64+qq*16+(l>>2), k0 = s*8+(l&3)
__global__ void k_wconv1(const float* __restrict__ W1){
  __shared__ float sw[256][16];
  int b=blockIdx.x; int kc=b&63, nb=(b>>6)&15, e=b>>10;
  int r=threadIdx.x;
  int srow = (r<128)? (nb*128+r) : (2048 + nb*128 + (r-128));  // h rows then gate rows
  const float4* src = (const float4*)(W1 + ((size_t)e*4096 + srow)*DM + kc*16);
  #pragma unroll
  for (int q4=0;q4<4;q4++){
    float4 v=src[q4];
    sw[r][q4*4+0]=rtf(v.x); sw[r][q4*4+1]=rtf(v.y); sw[r][q4*4+2]=rtf(v.z); sw[r][q4*4+3]=rtf(v.w);
  }
  __syncthreads();
  float* dst = g_W1p + ((size_t)(e*16+nb)*64 + kc)*4096;
  #pragma unroll
  for (int u=0;u<4;u++){
    int q=r*4+u;
    int cb=q>>8, s=(q>>7)&1, qq=(q>>5)&3, l=q&31;
    int n0=cb*64+qq*16+(l>>2), k0=s*8+(l&3);
    float4 v;
    v.x=sw[n0][k0];   v.y=sw[n0][k0+4];
    v.z=sw[n0+8][k0]; v.w=sw[n0+8][k0+4];
    *(float4*)(dst+q*4)=v;
  }
}
__global__ void k_wconv2(const float* __restrict__ W2){
  __shared__ float sw[128][16];
  int b=blockIdx.x; int kc=b&127, nb=(b>>7)&7, e=b>>10;
  int r=threadIdx.x;
  int srow = nb*128 + r;
  const float4* src = (const float4*)(W2 + ((size_t)e*1024 + srow)*DFF + kc*16);
  #pragma unroll
  for (int q4=0;q4<4;q4++){
    float4 v=src[q4];
    sw[r][q4*4+0]=rtf(v.x); sw[r][q4*4+1]=rtf(v.y); sw[r][q4*4+2]=rtf(v.z); sw[r][q4*4+3]=rtf(v.w);
  }
  __syncthreads();
  float* dst = g_W2p + ((size_t)(e*8+nb)*128 + kc)*2048;
  #pragma unroll
  for (int u=0;u<4;u++){
    int q=r*4+u;
    int cb=q>>8, s=(q>>7)&1, qq=(q>>5)&3, l=q&31;
    int n0=cb*64+qq*16+(l>>2), k0=s*8+(l&3);
    float4 v;
    v.x=sw[n0][k0];   v.y=sw[n0][k0+4];
    v.z=sw[n0+8][k0]; v.w=sw[n0+8][k0+4];
    *(float4*)(dst+q*4)=v;
  }
}

// ---------------- GEMM1: per (tile, nb) 128x256 (h||gate), K=1024, fused GLU ----------------
__global__ void __launch_bounds__(512,1) k_gemm1(){
  extern __shared__ float sm[];
  int tid=threadIdx.x, lane=tid&31, wid=tid>>5;
  int mw=wid&3, nw=wid>>2;               // 4 m-warps x 4 n-warps, warp tile 32x64
  int t=blockIdx.x>>4, nb=blockIdx.x&15;
  if (t>=g_tb[8]) return;
  int e=0;
  #pragma unroll
  for (int q=1;q<8;q++) if (t>=g_tb[q]) e=q;

  const float* Ab = g_Xr  + (size_t)t*(128*DM);
  const float* Bb = g_W1p + (size_t)(e*16+nb)*(64*4096);
  float* As = sm;                      // 4 stages x 2560 f32 (128 rows x 20)
  float* Bs = sm + 4*2560;             // 4 stages x 4096 f32
  uint32_t sb = su32(sm);
  uint32_t Asb = sb, Bsb = sb + 4*2560*4;

  float acc[2][8][4];
  #pragma unroll
  for (int i=0;i<2;i++)
    #pragma unroll
    for (int j=0;j<8;j++)
      #pragma unroll
      for (int c=0;c<4;c++) acc[i][j][c]=0.f;

  auto load = [&](int kb,int st){
    { int i=tid, r=i>>2, pc=i&3;
      cp16(Asb + (st*2560 + r*20 + pc*4)*4, Ab + (size_t)r*DM + kb*16 + pc*4); }
    #pragma unroll
    for (int z=0;z<2;z++){ int i=tid+z*512;
      cp16(Bsb + (st*4096 + i*4)*4, Bb + (size_t)kb*4096 + i*4); }
  };
  load(0,0); CPCOMMIT();
  load(1,1); CPCOMMIT();

  int r0 = mw*32 + (lane>>2), kl = lane&3;
  for (int kb=0;kb<64;kb++){
    int st=kb&3;
    if (kb+2<64) load(kb+2,(kb+2)&3);
    CPCOMMIT();
    CPWAIT(2);
    __syncthreads();
    const float* A_s = As + st*2560;
    const float* B_s = Bs + st*4096;
    #pragma unroll
    for (int s=0;s<2;s++){
      uint32_t a[2][4];
      #pragma unroll
      for (int mf=0;mf<2;mf++){
        const float* ap = A_s + (r0+mf*16)*20 + s*8 + kl;
        a[mf][0]=fu(ap[0]); a[mf][1]=fu(ap[160]); a[mf][2]=fu(ap[4]); a[mf][3]=fu(ap[164]);
      }
      const float* bp = B_s + nw*1024 + s*512 + lane*4;
      float4 q0=*(const float4*)bp, q1=*(const float4*)(bp+128),
             q2=*(const float4*)(bp+256), q3=*(const float4*)(bp+384);
      float qv[16]={q0.x,q0.y,q0.z,q0.w, q1.x,q1.y,q1.z,q1.w,
                    q2.x,q2.y,q2.z,q2.w, q3.x,q3.y,q3.z,q3.w};
      #pragma unroll
      for (int j=0;j<8;j++){
        uint32_t b0=fu(qv[(j>>1)*4+(j&1)*2]), b1=fu(qv[(j>>1)*4+(j&1)*2+1]);
        mma8(acc[0][j],a[0],b0,b1);
        mma8(acc[1][j],a[1],b0,b1);
      }
    }
  }
  CPWAIT(0);

  // ---- fused GLU epilogue: n-warps 0,1 hold h; 2,3 hold gate (same relative cols)
  float* G = sm;   // reuse stage memory: [64][132]
  #pragma unroll
  for (int w=0;w<2;w++){
    __syncthreads();
    if (nw>=2 && (mw>>1)==w){
      #pragma unroll
      for (int mf=0;mf<2;mf++){
        int sr=(mw&1)*32+mf*16+(lane>>2);
        #pragma unroll
        for (int j=0;j<8;j++){
          int col=(nw-2)*64+j*8+(lane&3)*2;
          G[sr*132+col]    =acc[mf][j][0]; G[sr*132+col+1]    =acc[mf][j][1];
          G[(sr+8)*132+col]=acc[mf][j][2]; G[(sr+8)*132+col+1]=acc[mf][j][3];
        }
      }
    }
    __syncthreads();
    if (nw<2 && (mw>>1)==w){
      #pragma unroll
      for (int mf=0;mf<2;mf++){
        #pragma unroll
        for (int hh=0;hh<2;hh++){
          int sr=(mw&1)*32+mf*16+(lane>>2)+hh*8;
          int row=w*64+sr;
          float* orow = g_ACT + (size_t)(t*128+row)*DFF + nb*128;
          #pragma unroll
          for (int j=0;j<8;j++){
            int col=nw*64+j*8+(lane&3)*2;
            float h0=acc[mf][j][hh*2], h1=acc[mf][j][hh*2+1];
            float g0=G[sr*132+col],    g1=G[sr*132+col+1];
            float a0=rtf(h0*g0*(1.f/(1.f+__expf(-g0))));
            float a1=rtf(h1*g1*(1.f/(1.f+__expf(-g1))));
            *(float2*)(orow+col)=make_float2(a0,a1);
          }
        }
      }
    }
  }
}

// ---------------- GEMM2: per (tile, nb) 128x128, K=2048, scatter epilogue ----------------
__global__ void __launch_bounds__(256,2) k_gemm2(float* __restrict__ out){
  extern __shared__ float sm[];
  int tid=threadIdx.x, lane=tid&31, wid=tid>>5;
  int mw=wid&3, nw=wid>>2;               // 4 m-warps x 2 n-warps
  int t=blockIdx.x>>3, nb=blockIdx.x&7;
  if (t>=g_tb[8]) return;
  int e=0;
  #pragma unroll
  for (int q=1;q<8;q++) if (t>=g_tb[q]) e=q;

  const float* Ab = g_ACT + (size_t)t*(128*DFF);
  const float* Bb = g_W2p + (size_t)(e*8+nb)*(128*2048);
  float* As = sm;
  float* Bs = sm + 4*2560;
  uint32_t sb = su32(sm);
  uint32_t Asb = sb, Bsb = sb + 4*2560*4;

  float acc[2][8][4];
  #pragma unroll
  for (int i=0;i<2;i++)
    #pragma unroll
    for (int j=0;j<8;j++)
      #pragma unroll
      for (int c=0;c<4;c++) acc[i][j][c]=0.f;

  auto load = [&](int kb,int st){
    #pragma unroll
    for (int z=0;z<2;z++){ int i=tid+z*256, r=i>>2, pc=i&3;
      cp16(Asb + (st*2560 + r*20 + pc*4)*4, Ab + (size_t)r*DFF + kb*16 + pc*4); }
    #pragma unroll
    for (int z=0;z<2;z++){ int i=tid+z*256;
      cp16(Bsb + (st*2048 + i*4)*4, Bb + (size_t)kb*2048 + i*4); }
  };
  load(0,0); CPCOMMIT();
  load(1,1); CPCOMMIT();

  int r0 = mw*32 + (lane>>2), kl = lane&3;
  for (int kb=0;kb<128;kb++){
    int st=kb&3;
    if (kb+2<128) load(kb+2,(kb+2)&3);
    CPCOMMIT();
    CPWAIT(2);
    __syncthreads();
    const float* A_s = As + st*2560;
    const float* B_s = Bs + st*2048;
    #pragma unroll
    for (int s=0;s<2;s++){
      uint32_t a[2][4];
      #pragma unroll
      for (int mf=0;mf<2;mf++){
        const float* ap = A_s + (r0+mf*16)*20 + s*8 + kl;
        a[mf][0]=fu(ap[0]); a[mf][1]=fu(ap[160]); a[mf][2]=fu(ap[4]); a[mf][3]=fu(ap[164]);
      }
      const float* bp = B_s + nw*1024 + s*512 + lane*4;
      float4 q0=*(const float4*)bp, q1=*(const float4*)(bp+128),
             q2=*(const float4*)(bp+256), q3=*(const float4*)(bp+384);
      float qv[16]={q0.x,q0.y,q0.z,q0.w, q1.x,q1.y,q1.z,q1.w,
                    q2.x,q2.y,q2.z,q2.w, q3.x,q3.y,q3.z,q3.w};
      #pragma unroll
      for (int j=0;j<8;j++){
        uint32_t b0=fu(qv[(j>>1)*4+(j&1)*2]), b1=fu(qv[(j>>1)*4+(j&1)*2+1]);
        mma8(acc[0][j],a[0],b0,b1);
        mma8(acc[1][j],a[1],b0,b1);
      }
    }
  }
  CPWAIT(0);

  // scatter epilogue
  #pragma unroll
  for (int mf=0;mf<2;mf++){
    #pragma unroll
    for (int hh=0;hh<2;hh++){
      int row=mw*32+mf*16+(lane>>2)+hh*8;
      int p=g_perm[t*128+row];
      if (p>=0){
        float* orow = out + (size_t)p*DM + nb*128 + nw*64;
        #pragma unroll
        for (int j=0;j<8;j++){
          int col=j*8+(lane&3)*2;
          *(float2*)(orow+col)=make_float2(acc[mf][j][hh*2],acc[mf][j][hh*2+1]);
        }
      }
    }
  }
}

// ---------------- host ----------------
extern "C" void kernel_launch(void* const* d_in, const int* in_sizes, int n_in,
                              void* d_out, int out_size){
  const float* x   = (const float*)d_in[0];
  const float* w1  = (const float*)d_in[1];
  const float* w2  = (const float*)d_in[2];
  const void*  ind = d_in[3];
  const int*   cnt = (const int*)d_in[4];
  float* out = (float*)d_out;
  (void)in_sizes; (void)n_in; (void)out_size;

  const int SM1 = (4*2560 + 4*4096)*4;   // 106496 B
  const int SM2 = (4*2560 + 4*2048)*4;   // 73728 B
  cudaFuncSetAttribute((const void*)k_gemm1, cudaFuncAttributeMaxDynamicSharedMemorySize, SM1);
  cudaFuncSetAttribute((const void*)k_gemm2, cudaFuncAttributeMaxDynamicSharedMemorySize, SM2);

  k_setupA<<<1, 32>>>(cnt);
  k_setupB<<<64, 256>>>();
  k_detect<<<32, 256>>>((const unsigned*)ind);
  k_gather<<<NROWS, 256>>>(x, ind);
  k_wconv1<<<8192, 256>>>(w1);
  k_wconv2<<<8192, 128>>>(w2);
  k_gemm1<<<MAXT*16, 512, SM1>>>();
  k_gemm2<<<MAXT*8,  256, SM2>>>(out);
}

// round 7
// speedup vs baseline: 1.1394x; 1.1394x over previous
#include <cuda_runtime.h>
#include <cstdint>

#define DM    1024
#define DFF   2048
#define NROWS 32768
#define MAXT  264
#define PADROWS (MAXT*128)

// ---------------- scratch ----------------
__device__ float g_Xp [(size_t)MAXT*128*DM];    // gathered x, tf32-rounded, FRAGMENT-PACKED
__device__ float g_ACT[(size_t)MAXT*128*DFF];   // GLU activations, FRAGMENT-PACKED
__device__ float g_W1p[(size_t)8*4096*DM];      // W1 packed B-frags (h||gate paired)
__device__ float g_W2p[(size_t)8*DM*DFF];       // W2 packed B-frags
__device__ int   g_perm[PADROWS];
__device__ int   g_cnt[8];
__device__ int   g_tb[9];
__device__ unsigned g_det;                      // 0 -> indices int64, else int32

// ---------------- helpers ----------------
__device__ __forceinline__ float rtf(float a){ asm("cvt.rna.tf32.f32 %0, %0;":"+f"(a)); return a; }
__device__ __forceinline__ uint32_t fu(float f){ return __float_as_uint(f); }
__device__ __forceinline__ uint32_t su32(const void* p){
  uint32_t a; asm("{ .reg .u64 t; cvta.to.shared.u64 t, %1; cvt.u32.u64 %0, t; }":"=r"(a):"l"(p)); return a;
}
__device__ __forceinline__ void cp16(uint32_t d, const void* s){
  asm volatile("cp.async.cg.shared.global [%0], [%1], 16;" :: "r"(d), "l"(s) : "memory");
}
#define CPCOMMIT() asm volatile("cp.async.commit_group;":::"memory")
#define CPWAIT(n)  asm volatile("cp.async.wait_group %0;"::"n"(n):"memory")

__device__ __forceinline__ void mma8(float* c, const uint32_t* a, uint32_t b0, uint32_t b1){
  asm volatile("mma.sync.aligned.m16n8k8.row.col.f32.tf32.tf32.f32 "
    "{%0,%1,%2,%3},{%4,%5,%6,%7},{%8,%9},{%0,%1,%2,%3};"
    : "+f"(c[0]),"+f"(c[1]),"+f"(c[2]),"+f"(c[3])
    : "r"(a[0]),"r"(a[1]),"r"(a[2]),"r"(a[3]),"r"(b0),"r"(b1));
}

// ---------------- setup ----------------
__global__ void k_setupA(const int* __restrict__ counts){
  if (threadIdx.x==0){
    int tb=0;
    for (int e=0;e<8;e++){ g_tb[e]=tb; g_cnt[e]=0; tb += (counts[e]+127)>>7; }
    g_tb[8]=tb;
    g_det = 0u;
  }
}
__global__ void k_setupB(){
  for (int i = blockIdx.x*blockDim.x + threadIdx.x; i<PADROWS; i += gridDim.x*blockDim.x)
    g_perm[i] = -1;
}
__global__ void k_detect(const unsigned* __restrict__ w){
  unsigned v = 0;
  for (int i = blockIdx.x*blockDim.x + threadIdx.x; i < 16384; i += gridDim.x*blockDim.x)
    v |= w[2*i+1];
  #pragma unroll
  for (int o=16;o>0;o>>=1) v |= __shfl_xor_sync(0xFFFFFFFFu, v, o);
  if ((threadIdx.x&31)==0 && v) atomicOr(&g_det, v);
}
__global__ void k_perm(const void* __restrict__ ind){
  int p = blockIdx.x*blockDim.x + threadIdx.x;
  if (p>=NROWS) return;
  int e;
  if (g_det==0u) e = (int)((const long long*)ind)[p];
  else           e = ((const int*)ind)[p];
  e &= 7;
  int s = (g_tb[e]<<7) + atomicAdd(&g_cnt[e],1);
  if (s >= PADROWS) s = PADROWS-1;
  g_perm[s] = p;
}

// ---------------- packA: gather + round + fragment-pack ----------------
// Packed A layout per tile: float4 fid = kb*512 + s*256 + g*32 + l
//   value = { A(16g+q, K0), A(16g+q+8, K0), A(16g+q, K0+4), A(16g+q+8, K0+4) }
//   q=l>>2, K0 = kb*16 + s*8 + (l&3)
__global__ void __launch_bounds__(256,1) k_packA(const float* __restrict__ x){
  __shared__ int sp[128];
  extern __shared__ float sm[];   // [128][132]
  int t = blockIdx.x>>3, kb8 = blockIdx.x&7;
  if (t>=g_tb[8]) return;
  int tid=threadIdx.x;
  if (tid<128) sp[tid]=g_perm[t*128+tid];
  __syncthreads();
  // phase 1: stage 128 rows x 128 cols (= 4096 float4) of x into SMEM
  #pragma unroll
  for (int v=0;v<16;v++){
    int i=v*256+tid, row=i>>5, c4=i&31;
    int p=sp[row];
    float4 fv=make_float4(0.f,0.f,0.f,0.f);
    if (p>=0){
      fv = *(const float4*)(x + (size_t)(p>>1)*DM + kb8*128 + c4*4);
      fv.x=rtf(fv.x); fv.y=rtf(fv.y); fv.z=rtf(fv.z); fv.w=rtf(fv.w);
    }
    *(float4*)(sm + row*132 + c4*4) = fv;
  }
  __syncthreads();
  // phase 2: fragment-pack
  float* dst = g_Xp + (size_t)t*(128*DM);
  #pragma unroll
  for (int v=0;v<16;v++){
    int o=v*256+tid;
    int kcl=o>>9, s2=(o>>8)&1, g=(o>>5)&7, l=o&31, q=l>>2, kl=l&3;
    int row=16*g+q, col=kcl*16+s2*8+kl;
    float4 fv;
    fv.x=sm[row*132+col];     fv.y=sm[(row+8)*132+col];
    fv.z=sm[row*132+col+4];   fv.w=sm[(row+8)*132+col+4];
    int kb=kb8*8+kcl;
    *(float4*)(dst + ((size_t)kb*512 + s2*256 + g*32 + l)*4) = fv;
  }
}

// ---------------- weight pack kernels ----------------
__global__ void k_wconv1(const float* __restrict__ W1){
  __shared__ float sw[256][16];
  int b=blockIdx.x; int kc=b&63, nb=(b>>6)&15, e=b>>10;
  int r=threadIdx.x;
  int srow = (r<128)? (nb*128+r) : (2048 + nb*128 + (r-128));
  const float4* src = (const float4*)(W1 + ((size_t)e*4096 + srow)*DM + kc*16);
  #pragma unroll
  for (int q4=0;q4<4;q4++){
    float4 v=src[q4];
    sw[r][q4*4+0]=rtf(v.x); sw[r][q4*4+1]=rtf(v.y); sw[r][q4*4+2]=rtf(v.z); sw[r][q4*4+3]=rtf(v.w);
  }
  __syncthreads();
  float* dst = g_W1p + ((size_t)(e*16+nb)*64 + kc)*4096;
  #pragma unroll
  for (int u=0;u<4;u++){
    int q=r*4+u;
    int cb=q>>8, s=(q>>7)&1, qq=(q>>5)&3, l=q&31;
    int n0=cb*64+qq*16+(l>>2), k0=s*8+(l&3);
    float4 v;
    v.x=sw[n0][k0];   v.y=sw[n0][k0+4];
    v.z=sw[n0+8][k0]; v.w=sw[n0+8][k0+4];
    *(float4*)(dst+q*4)=v;
  }
}
__global__ void k_wconv2(const float* __restrict__ W2){
  __shared__ float sw[128][16];
  int b=blockIdx.x; int kc=b&127, nb=(b>>7)&7, e=b>>10;
  int r=threadIdx.x;
  int srow = nb*128 + r;
  const float4* src = (const float4*)(W2 + ((size_t)e*1024 + srow)*DFF + kc*16);
  #pragma unroll
  for (int q4=0;q4<4;q4++){
    float4 v=src[q4];
    sw[r][q4*4+0]=rtf(v.x); sw[r][q4*4+1]=rtf(v.y); sw[r][q4*4+2]=rtf(v.z); sw[r][q4*4+3]=rtf(v.w);
  }
  __syncthreads();
  float* dst = g_W2p + ((size_t)(e*8+nb)*128 + kc)*2048;
  #pragma unroll
  for (int u=0;u<4;u++){
    int q=r*4+u;
    int cb=q>>8, s=(q>>7)&1, qq=(q>>5)&3, l=q&31;
    int n0=cb*64+qq*16+(l>>2), k0=s*8+(l&3);
    float4 v;
    v.x=sw[n0][k0];   v.y=sw[n0][k0+4];
    v.z=sw[n0+8][k0]; v.w=sw[n0+8][k0+4];
    *(float4*)(dst+q*4)=v;
  }
}

// ---------------- unified GEMM: 128x256 tile, 512 threads, 4-stage ----------------
template<bool IS1>
__global__ void __launch_bounds__(512,1) k_gemm(float* __restrict__ out){
  constexpr int NKB = IS1 ? 64 : 128;
  extern __shared__ float sm[];
  int tid=threadIdx.x, lane=tid&31, wid=tid>>5;
  int mw=wid&3, nw=wid>>2;
  int t, nb;
  if (IS1){ t=blockIdx.x>>4; nb=blockIdx.x&15; }
  else    { t=blockIdx.x>>2; nb=blockIdx.x&3;  }
  if (t>=g_tb[8]) return;
  int e=0;
  #pragma unroll
  for (int q=1;q<8;q++) if (t>=g_tb[q]) e=q;

  const float* Ab = (IS1? g_Xp : g_ACT) + (size_t)t*(size_t)(128*(IS1?DM:DFF));
  const float *B0, *B1=nullptr;
  if (IS1) B0 = g_W1p + (size_t)(e*16+nb)*(64*4096);
  else   { B0 = g_W2p + (size_t)(e*8+2*nb)*(128*2048); B1 = B0 + (size_t)128*2048; }

  uint32_t sb = su32(sm);
  uint32_t Asb = sb, Bsb = sb + 32768;   // A: 4x2048 f32, B: 4x4096 f32

  float acc[2][8][4];
  #pragma unroll
  for (int i=0;i<2;i++)
    #pragma unroll
    for (int j=0;j<8;j++)
      #pragma unroll
      for (int c=0;c<4;c++) acc[i][j][c]=0.f;

  auto load = [&](int kb,int st){
    cp16(Asb + st*8192 + tid*16, Ab + (size_t)kb*2048 + tid*4);
    if (IS1){
      cp16(Bsb + st*16384 +        tid*16, B0 + (size_t)kb*4096 +        tid*4);
      cp16(Bsb + st*16384 + 8192 + tid*16, B0 + (size_t)kb*4096 + 2048 + tid*4);
    } else {
      cp16(Bsb + st*16384 +        tid*16, B0 + (size_t)kb*2048 + tid*4);
      cp16(Bsb + st*16384 + 8192 + tid*16, B1 + (size_t)kb*2048 + tid*4);
    }
  };
  load(0,0); CPCOMMIT();
  load(1,1); CPCOMMIT();
  load(2,2); CPCOMMIT();

  for (int kb=0; kb<NKB; kb++){
    int st=kb&3;
    CPWAIT(2);
    __syncthreads();
    const float* A_s = sm + st*2048;
    const float* B_s = sm + 8192 + st*4096;
    #pragma unroll
    for (int s=0;s<2;s++){
      float4 af0 = *(const float4*)(A_s + s*1024 + (2*mw+0)*128 + lane*4);
      float4 af1 = *(const float4*)(A_s + s*1024 + (2*mw+1)*128 + lane*4);
      const float* bp = B_s + nw*1024 + s*512 + lane*4;
      float4 q0=*(const float4*)bp,       q1=*(const float4*)(bp+128),
             q2=*(const float4*)(bp+256), q3=*(const float4*)(bp+384);
      if (s==0){                                   // exactly ONE commit per kb iteration:
        if (kb+3<NKB) load(kb+3,(kb+3)&3);         // empty groups at the tail keep the
        CPCOMMIT();                                // wait_group(2) drain invariant valid
      }
      uint32_t a0[4]={fu(af0.x),fu(af0.y),fu(af0.z),fu(af0.w)};
      uint32_t a1[4]={fu(af1.x),fu(af1.y),fu(af1.z),fu(af1.w)};
      float qv[16]={q0.x,q0.y,q0.z,q0.w, q1.x,q1.y,q1.z,q1.w,
                    q2.x,q2.y,q2.z,q2.w, q3.x,q3.y,q3.z,q3.w};
      #pragma unroll
      for (int j=0;j<8;j++){
        uint32_t b0=fu(qv[(j>>1)*4+(j&1)*2]), b1=fu(qv[(j>>1)*4+(j&1)*2+1]);
        mma8(acc[0][j],a0,b0,b1);
        mma8(acc[1][j],a1,b0,b1);
      }
    }
  }
  CPWAIT(0);
  __syncthreads();

  if (IS1){
    // GLU epilogue -> fragment-packed g_ACT (this nb covers ACT cols nb*128..+127)
    float* G  = sm;
    float* Gt = sm + 64*132;
    float* actb = g_ACT + (size_t)t*(128*DFF);
    #pragma unroll
    for (int w=0;w<2;w++){
      if ((mw>>1)==w && nw>=2){
        #pragma unroll
        for (int mf=0;mf<2;mf++){
          int sr=(mw&1)*32+mf*16+(lane>>2);
          #pragma unroll
          for (int j=0;j<8;j++){
            int col=(nw-2)*64+j*8+(lane&3)*2;
            G[sr*132+col]    =acc[mf][j][0]; G[sr*132+col+1]    =acc[mf][j][1];
            G[(sr+8)*132+col]=acc[mf][j][2]; G[(sr+8)*132+col+1]=acc[mf][j][3];
          }
        }
      }
      __syncthreads();
      if ((mw>>1)==w && nw<2){
        #pragma unroll
        for (int mf=0;mf<2;mf++){
          int sr=(mw&1)*32+mf*16+(lane>>2);
          #pragma unroll
          for (int j=0;j<8;j++){
            int col=nw*64+j*8+(lane&3)*2;
            float g0=G[sr*132+col],     g1=G[sr*132+col+1];
            float g2=G[(sr+8)*132+col], g3=G[(sr+8)*132+col+1];
            Gt[sr*132+col]      = rtf(acc[mf][j][0]*g0*(1.f/(1.f+__expf(-g0))));
            Gt[sr*132+col+1]    = rtf(acc[mf][j][1]*g1*(1.f/(1.f+__expf(-g1))));
            Gt[(sr+8)*132+col]  = rtf(acc[mf][j][2]*g2*(1.f/(1.f+__expf(-g2))));
            Gt[(sr+8)*132+col+1]= rtf(acc[mf][j][3]*g3*(1.f/(1.f+__expf(-g3))));
          }
        }
      }
      __syncthreads();
      // packed write: 2048 float4 per half (kcl 0..7, s2 0..1, g 0..3, l 0..31)
      #pragma unroll
      for (int v=0;v<4;v++){
        int o=v*512+tid;
        int kcl=o>>8, s2=(o>>7)&1, g=(o>>5)&3, l=o&31, q=l>>2, kl=l&3;
        int row=g*16+q, col=kcl*16+s2*8+kl;
        float4 fv;
        fv.x=Gt[row*132+col];     fv.y=Gt[(row+8)*132+col];
        fv.z=Gt[row*132+col+4];   fv.w=Gt[(row+8)*132+col+4];
        int kb=nb*8+kcl, gg=w*4+g;
        *(float4*)(actb + ((size_t)kb*512 + s2*256 + gg*32 + l)*4) = fv;
      }
      __syncthreads();
    }
  } else {
    // scatter epilogue
    #pragma unroll
    for (int mf=0;mf<2;mf++){
      int r=mw*32+mf*16+(lane>>2);
      int p0=g_perm[t*128+r], p1=g_perm[t*128+r+8];
      #pragma unroll
      for (int j=0;j<8;j++){
        int col=nb*256+nw*64+j*8+(lane&3)*2;
        if (p0>=0) *(float2*)(out+(size_t)p0*DM+col)=make_float2(acc[mf][j][0],acc[mf][j][1]);
        if (p1>=0) *(float2*)(out+(size_t)p1*DM+col)=make_float2(acc[mf][j][2],acc[mf][j][3]);
      }
    }
  }
}

// ---------------- host ----------------
extern "C" void kernel_launch(void* const* d_in, const int* in_sizes, int n_in,
                              void* d_out, int out_size){
  const float* x   = (const float*)d_in[0];
  const float* w1  = (const float*)d_in[1];
  const float* w2  = (const float*)d_in[2];
  const void*  ind = d_in[3];
  const int*   cnt = (const int*)d_in[4];
  float* out = (float*)d_out;
  (void)in_sizes; (void)n_in; (void)out_size;

  const int SMG = (4*2048 + 4*4096)*4;   // 98304 B
  const int SMP = 128*132*4;             // 67584 B
  cudaFuncSetAttribute((const void*)k_gemm<true>,  cudaFuncAttributeMaxDynamicSharedMemorySize, SMG);
  cudaFuncSetAttribute((const void*)k_gemm<false>, cudaFuncAttributeMaxDynamicSharedMemorySize, SMG);
  cudaFuncSetAttribute((const void*)k_packA, cudaFuncAttributeMaxDynamicSharedMemorySize, SMP);

  k_setupA<<<1, 32>>>(cnt);
  k_setupB<<<64, 256>>>();
  k_detect<<<32, 256>>>((const unsigned*)ind);
  k_perm<<<128, 256>>>(ind);
  k_packA<<<MAXT*8, 256, SMP>>>(x);
  k_wconv1<<<8192, 256>>>(w1);
  k_wconv2<<<8192, 128>>>(w2);
  k_gemm<true ><<<MAXT*16, 512, SMG>>>(nullptr);
  k_gemm<false><<<MAXT*4,  512, SMG>>>(out);
}